// round 10
// baseline (speedup 1.0000x reference)
#include <cuda_runtime.h>
#include <cstdint>

#define BATCH 32
#define CIN   256
#define COUT  256
#define HH_   56
#define WW_   56
#define HW_   (HH_*WW_)
#define NPOS  (BATCH*HW_)

// ---------------- device scratch ----------------
__device__ uint4 g_xpack[NPOS * 2];        // [pos][2]: 8 u32 sign bits (bit=1 iff x>=0)
__device__ uint4 g_wpack[COUT * 9 * 2];    // [cout*9+tap][2]

// ---------------- fused pack kernel ----------------
__global__ void pack_all_kernel(const float* __restrict__ x,
                                const float* __restrict__ wgt) {
    if (blockIdx.x < 392) {                       // 392*256 == NPOS exactly
        int pos = blockIdx.x * 256 + threadIdx.x;
        int b  = pos / HW_;
        int hw = pos - b * HW_;
        const float* xp = x + (size_t)b * CIN * HW_ + hw;
        uint32_t wds[8];
        #pragma unroll
        for (int k = 0; k < 8; ++k) {
            uint32_t wd = 0;
            #pragma unroll
            for (int i = 0; i < 32; ++i) {
                float v = xp[(size_t)(k * 32 + i) * HW_];
                wd |= (v >= 0.0f ? 1u : 0u) << i;
            }
            wds[k] = wd;
        }
        g_xpack[pos * 2 + 0] = make_uint4(wds[0], wds[1], wds[2], wds[3]);
        g_xpack[pos * 2 + 1] = make_uint4(wds[4], wds[5], wds[6], wds[7]);
    } else {
        int idx = (blockIdx.x - 392) * 256 + threadIdx.x;   // cout*9+tap
        if (idx >= COUT * 9) return;
        int cout = idx / 9;
        int tap  = idx - cout * 9;
        const float* wp = wgt + (size_t)cout * CIN * 9 + tap;
        uint32_t wds[8];
        #pragma unroll
        for (int k = 0; k < 8; ++k) {
            uint32_t wd = 0;
            #pragma unroll
            for (int i = 0; i < 32; ++i) {
                float v = wp[(size_t)(k * 32 + i) * 9];
                wd |= (v >= 0.0f ? 1u : 0u) << i;
            }
            wds[k] = wd;
        }
        g_wpack[idx * 2 + 0] = make_uint4(wds[0], wds[1], wds[2], wds[3]);
        g_wpack[idx * 2 + 1] = make_uint4(wds[4], wds[5], wds[6], wds[7]);
    }
}

// ---------------- main conv: half cin split, 32 warps/SM, pair stores --------
// Block = 256 threads = 8 warps. Lane = half*16 + csub.
//   csub (0..15) -> cout = bz*128 + wid*16 + csub;  half (0..1) -> cin words 4h..4h+3.
// Block computes one (b, h) output row for 128 couts.
__global__ void __launch_bounds__(256, 4)
bconv_pop_kernel(const float* __restrict__ bias, float* __restrict__ out) {
    __shared__ uint4 xs[3 * WW_ * 2];     // [row][v][half]

    const int tid  = threadIdx.x;
    const int lane = tid & 31;
    const int wid  = tid >> 5;
    const int half = lane >> 4;
    const int csub = lane & 15;
    const int h    = blockIdx.x;
    const int b    = blockIdx.y;
    const int cout = blockIdx.z * 128 + wid * 16 + csub;

    const bool rv0 = (h > 0), rv2 = (h < HH_ - 1);

    // ---- stage x (3 rows x 56 cols x 2 halves), zero-fill invalid rows ----
    for (int i = tid; i < 3 * WW_ * 2; i += 256) {
        int row = i / (WW_ * 2);
        int rem = i - row * (WW_ * 2);
        int v = rem >> 1, j = rem & 1;
        int rin = h - 1 + row;
        uint4 val = make_uint4(0u, 0u, 0u, 0u);
        if (rin >= 0 && rin < HH_)
            val = g_xpack[((size_t)(b * HH_ + rin) * WW_ + v) * 2 + j];
        xs[(row * WW_ + v) * 2 + j] = val;
    }

    // ---- per-lane half-weights in registers (36 regs) ----
    uint32_t wreg[9][4];
    #pragma unroll
    for (int t = 0; t < 9; ++t) {
        uint4 a = g_wpack[(cout * 9 + t) * 2 + half];
        wreg[t][0] = a.x; wreg[t][1] = a.y; wreg[t][2] = a.z; wreg[t][3] = a.w;
    }
    const float bv = bias[cout];

    // ---- per-half pad-correction constants ----
    int pm[3], pl[3], pr[3];
    #pragma unroll
    for (int dh = 0; dh < 3; ++dh) {
        int p0 = 0, p1 = 0, p2 = 0;
        #pragma unroll
        for (int k = 0; k < 4; ++k) {
            p0 += __popc(wreg[dh * 3 + 0][k]);
            p1 += __popc(wreg[dh * 3 + 1][k]);
            p2 += __popc(wreg[dh * 3 + 2][k]);
        }
        pm[dh] = p0 + p1 + p2; pl[dh] = p1 + p2; pr[dh] = p0 + p1;
    }
    const int nrows = (int)rv0 + 1 + (int)rv2;
    const int cmid   = 384 * nrows + 2 * ((rv0 ? 0 : pm[0]) + (rv2 ? 0 : pm[2]));
    const int cleft  = 256 * nrows + 2 * ((rv0 ? 0 : pl[0]) + (rv2 ? 0 : pl[2]));
    const int cright = 256 * nrows + 2 * ((rv0 ? 0 : pr[0]) + (rv2 ? 0 : pr[2]));

    __syncthreads();

    float* obase = out + ((size_t)(b * COUT + cout) * HH_ + h) * WW_;

    int ring[4] = {0, 0, 0, 0};
    float fb0 = 0.0f, fb1;

    // v = input column. x col v feeds outputs w = v+1-dw, dw in {0,1,2}.
    // Output w completes at end of step v = w+1; completions are in w-order.
    for (int v0 = 0; v0 < 7; ++v0) {
        #pragma unroll
        for (int u = 0; u < 8; ++u) {
            const int v = v0 * 8 + u;
            int addn = 0, addm = 0, addo = 0;
            #pragma unroll
            for (int row = 0; row < 3; ++row) {
                uint4 xa = xs[(row * WW_ + v) * 2 + half];
                uint32_t xw[4] = {xa.x, xa.y, xa.z, xa.w};
                #pragma unroll
                for (int k = 0; k < 4; ++k) {
                    addn += __popc(xw[k] ^ wreg[row * 3 + 0][k]);
                    addm += __popc(xw[k] ^ wreg[row * 3 + 1][k]);
                    addo += __popc(xw[k] ^ wreg[row * 3 + 2][k]);
                }
            }
            ring[(u + 1) & 3] += addn;      // w = v+1
            ring[u & 3]       += addm;      // w = v
            ring[(u + 3) & 3] += addo;      // w = v-1 (completes now)

            if (v == 0) {
                ring[3] = 0;                // discard w=-1 garbage
            } else {
                const int cw   = v - 1;     // completed output index
                const int slot = (u + 3) & 3;
                const int c    = (cw == 0) ? cleft : cmid;
                int comb = c - 2 * ring[slot];
                comb += __shfl_xor_sync(0xffffffffu, comb, 16);
                ring[slot] = 0;
                if (cw & 1) {
                    fb1 = (float)comb + bv;
                    if (half == 0)
                        *(float2*)(obase + cw - 1) = make_float2(fb0, fb1);
                } else {
                    fb0 = (float)comb + bv;
                }
            }
        }
    }
    // tail: w = 55 (edge) sits in slot 55&3 = 2... ring slot for w=55: completes
    // outside loop; w=55 index slot = (55) % 4 ... accumulated as "w=v+1" and
    // "w=v" contributions into slot (55 & 3) = 3.
    {
        int comb = cright - 2 * ring[3];
        comb += __shfl_xor_sync(0xffffffffu, comb, 16);
        fb1 = (float)comb + bv;
        if (half == 0)
            *(float2*)(obase + 54) = make_float2(fb0, fb1);
    }
}

// ---------------------------------------------------------------------------
extern "C" void kernel_launch(void* const* d_in, const int* in_sizes, int n_in,
                              void* d_out, int out_size) {
    const float* x    = (const float*)d_in[0];
    const float* wgt  = (const float*)d_in[1];
    const float* bias = (const float*)d_in[2];
    float* out = (float*)d_out;

    pack_all_kernel<<<401, 256>>>(x, wgt);
    dim3 grid(HH_, BATCH, 2);
    bconv_pop_kernel<<<grid, 256>>>(bias, out);
}

// round 11
// speedup vs baseline: 1.6114x; 1.6114x over previous
#include <cuda_runtime.h>
#include <cstdint>

#define BATCH 32
#define CIN   256
#define COUT  256
#define HH_   56
#define WW_   56
#define HW_   (HH_*WW_)
#define NPOS  (BATCH*HW_)

// ---------------- device scratch ----------------
__device__ uint4 g_xpack[NPOS * 2];        // [pos][2]: 8 u32 sign bits (bit=1 iff x>=0)
__device__ uint4 g_wpack[COUT * 9 * 2];    // [cout*9+tap][2]
__device__ int   g_one = 1;                // opaque 1 -> genuine IMAD on fma pipe

// ---------------- fused pack kernel ----------------
__global__ void pack_all_kernel(const float* __restrict__ x,
                                const float* __restrict__ wgt) {
    if (blockIdx.x < 392) {                       // 392*256 == NPOS exactly
        int pos = blockIdx.x * 256 + threadIdx.x;
        int b  = pos / HW_;
        int hw = pos - b * HW_;
        const float* xp = x + (size_t)b * CIN * HW_ + hw;
        uint32_t wds[8];
        #pragma unroll
        for (int k = 0; k < 8; ++k) {
            uint32_t wd = 0;
            #pragma unroll
            for (int i = 0; i < 32; ++i) {
                float v = xp[(size_t)(k * 32 + i) * HW_];
                wd |= (v >= 0.0f ? 1u : 0u) << i;
            }
            wds[k] = wd;
        }
        g_xpack[pos * 2 + 0] = make_uint4(wds[0], wds[1], wds[2], wds[3]);
        g_xpack[pos * 2 + 1] = make_uint4(wds[4], wds[5], wds[6], wds[7]);
    } else {
        int idx = (blockIdx.x - 392) * 256 + threadIdx.x;   // cout*9+tap
        if (idx >= COUT * 9) return;
        int cout = idx / 9;
        int tap  = idx - cout * 9;
        const float* wp = wgt + (size_t)cout * CIN * 9 + tap;
        uint32_t wds[8];
        #pragma unroll
        for (int k = 0; k < 8; ++k) {
            uint32_t wd = 0;
            #pragma unroll
            for (int i = 0; i < 32; ++i) {
                float v = wp[(size_t)(k * 32 + i) * 9];
                wd |= (v >= 0.0f ? 1u : 0u) << i;
            }
            wds[k] = wd;
        }
        g_wpack[idx * 2 + 0] = make_uint4(wds[0], wds[1], wds[2], wds[3]);
        g_wpack[idx * 2 + 1] = make_uint4(wds[4], wds[5], wds[6], wds[7]);
    }
}

// d = a + b executed as IMAD on the fma pipe (one is a runtime 1)
#define PADD(d, a, b) \
    asm("mad.lo.s32 %0, %1, %2, %3;" : "=r"(d) : "r"(a), "r"(one), "r"(b))
// acc += a on the fma pipe
#define PACC(acc, a) \
    asm("mad.lo.s32 %0, %1, %2, %0;" : "+r"(acc) : "r"(a), "r"(one))

// ---------------- main conv: half cin split, fma-pipe reduction tree ---------
// Block = 256 threads = 8 warps. Lane = half*16 + csub.
//   csub (0..15) -> cout = bz*128 + wid*16 + csub;  half -> cin words 4h..4h+3.
__global__ void __launch_bounds__(256, 3)
bconv_pop_kernel(const float* __restrict__ bias, float* __restrict__ out) {
    __shared__ uint4 xs[3 * WW_ * 2];     // [row][v][half]

    const int tid  = threadIdx.x;
    const int lane = tid & 31;
    const int wid  = tid >> 5;
    const int half = lane >> 4;
    const int csub = lane & 15;
    const int h    = blockIdx.x;
    const int b    = blockIdx.y;
    const int cout = blockIdx.z * 128 + wid * 16 + csub;

    const bool rv0 = (h > 0), rv2 = (h < HH_ - 1);
    const int one = *(volatile int*)&g_one;

    // ---- stage x (3 rows x 56 cols x 2 halves), zero-fill invalid rows ----
    for (int i = tid; i < 3 * WW_ * 2; i += 256) {
        int row = i / (WW_ * 2);
        int rem = i - row * (WW_ * 2);
        int v = rem >> 1, j = rem & 1;
        int rin = h - 1 + row;
        uint4 val = make_uint4(0u, 0u, 0u, 0u);
        if (rin >= 0 && rin < HH_)
            val = g_xpack[((size_t)(b * HH_ + rin) * WW_ + v) * 2 + j];
        xs[(row * WW_ + v) * 2 + j] = val;
    }

    // ---- per-lane half-weights in registers (36 regs) ----
    uint32_t wreg[9][4];
    #pragma unroll
    for (int t = 0; t < 9; ++t) {
        uint4 a = g_wpack[(cout * 9 + t) * 2 + half];
        wreg[t][0] = a.x; wreg[t][1] = a.y; wreg[t][2] = a.z; wreg[t][3] = a.w;
    }
    const float bv = bias[cout];

    // ---- per-half pad-correction constants ----
    int pm[3], pl[3], pr[3];
    #pragma unroll
    for (int dh = 0; dh < 3; ++dh) {
        int p0 = 0, p1 = 0, p2 = 0;
        #pragma unroll
        for (int k = 0; k < 4; ++k) {
            p0 += __popc(wreg[dh * 3 + 0][k]);
            p1 += __popc(wreg[dh * 3 + 1][k]);
            p2 += __popc(wreg[dh * 3 + 2][k]);
        }
        pm[dh] = p0 + p1 + p2; pl[dh] = p1 + p2; pr[dh] = p0 + p1;
    }
    const int nrows = (int)rv0 + 1 + (int)rv2;
    const int cmid   = 384 * nrows + 2 * ((rv0 ? 0 : pm[0]) + (rv2 ? 0 : pm[2]));
    const int cleft  = 256 * nrows + 2 * ((rv0 ? 0 : pl[0]) + (rv2 ? 0 : pl[2]));
    const int cright = 256 * nrows + 2 * ((rv0 ? 0 : pr[0]) + (rv2 ? 0 : pr[2]));

    __syncthreads();

    float* obase = out + ((size_t)(b * COUT + cout) * HH_ + h) * WW_;

    int ring[4] = {0, 0, 0, 0};
    float fb[8];

    for (int v0 = 0; v0 < 7; ++v0) {
        #pragma unroll
        for (int u = 0; u < 8; ++u) {
            const int v = v0 * 8 + u;

            // 36 XOR+POPC (alu) with pairwise sums on the fma pipe
            int sn[2], sm[2], so[2];
            #pragma unroll
            for (int g = 0; g < 2; ++g) {      // word pairs (0,1) and (2,3)
                int n0, n1, m0, m1, o0, o1;
                {
                    uint4 xa = xs[(0 * WW_ + v) * 2 + half];
                    uint32_t x0 = (g == 0) ? xa.x : xa.z;
                    uint32_t x1 = (g == 0) ? xa.y : xa.w;
                    PADD(n0, __popc(x0 ^ wreg[0][2*g]), __popc(x1 ^ wreg[0][2*g+1]));
                    PADD(m0, __popc(x0 ^ wreg[1][2*g]), __popc(x1 ^ wreg[1][2*g+1]));
                    PADD(o0, __popc(x0 ^ wreg[2][2*g]), __popc(x1 ^ wreg[2][2*g+1]));
                }
                {
                    uint4 xa = xs[(1 * WW_ + v) * 2 + half];
                    uint32_t x0 = (g == 0) ? xa.x : xa.z;
                    uint32_t x1 = (g == 0) ? xa.y : xa.w;
                    PACC(n0, __popc(x0 ^ wreg[3][2*g]));
                    PACC(n0, __popc(x1 ^ wreg[3][2*g+1]));
                    PADD(m1, __popc(x0 ^ wreg[4][2*g]), __popc(x1 ^ wreg[4][2*g+1]));
                    PADD(o1, __popc(x0 ^ wreg[5][2*g]), __popc(x1 ^ wreg[5][2*g+1]));
                }
                {
                    uint4 xa = xs[(2 * WW_ + v) * 2 + half];
                    uint32_t x0 = (g == 0) ? xa.x : xa.z;
                    uint32_t x1 = (g == 0) ? xa.y : xa.w;
                    PADD(n1, __popc(x0 ^ wreg[6][2*g]), __popc(x1 ^ wreg[6][2*g+1]));
                    PACC(m1, __popc(x0 ^ wreg[7][2*g]));
                    PACC(m1, __popc(x1 ^ wreg[7][2*g+1]));
                    PACC(o1, __popc(x0 ^ wreg[8][2*g]));
                    PACC(o1, __popc(x1 ^ wreg[8][2*g+1]));
                }
                sn[g] = n0 + n1;               // IADD3-friendly (alu)
                sm[g] = m0 + m1;
                so[g] = o0 + o1;
            }
            PACC(ring[(u + 1) & 3], sn[0] + sn[1]);   // w = v+1
            PACC(ring[u & 3],       sm[0] + sm[1]);   // w = v
            PACC(ring[(u + 3) & 3], so[0] + so[1]);   // w = v-1 (completes)

            if (u == 0) {
                if (v0 == 0) {
                    ring[3] = 0;            // discard w=-1 garbage
                } else {
                    int comb = cmid - 2 * ring[3];
                    comb += __shfl_xor_sync(0xffffffffu, comb, 16);
                    fb[7] = (float)comb + bv;
                    ring[3] = 0;
                    if (half == 0) {
                        *(float4*)(obase + (v0 - 1) * 8)     = make_float4(fb[0], fb[1], fb[2], fb[3]);
                        *(float4*)(obase + (v0 - 1) * 8 + 4) = make_float4(fb[4], fb[5], fb[6], fb[7]);
                    }
                }
            } else {
                const int slot = (u + 3) & 3;
                int c = cmid;
                if (u == 1) c = (v0 == 0) ? cleft : cmid;   // w==0 edge
                int comb = c - 2 * ring[slot];
                comb += __shfl_xor_sync(0xffffffffu, comb, 16);
                fb[(u - 1) & 7] = (float)comb + bv;
                ring[slot] = 0;
            }
        }
    }
    // tail: w = 55 (edge) sits in slot 3
    {
        int comb = cright - 2 * ring[3];
        comb += __shfl_xor_sync(0xffffffffu, comb, 16);
        fb[7] = (float)comb + bv;
    }
    if (half == 0) {
        *(float4*)(obase + 48) = make_float4(fb[0], fb[1], fb[2], fb[3]);
        *(float4*)(obase + 52) = make_float4(fb[4], fb[5], fb[6], fb[7]);
    }
}

// ---------------------------------------------------------------------------
extern "C" void kernel_launch(void* const* d_in, const int* in_sizes, int n_in,
                              void* d_out, int out_size) {
    const float* x    = (const float*)d_in[0];
    const float* wgt  = (const float*)d_in[1];
    const float* bias = (const float*)d_in[2];
    float* out = (float*)d_out;

    pack_all_kernel<<<401, 256>>>(x, wgt);
    dim3 grid(HH_, BATCH, 2);
    bconv_pop_kernel<<<grid, 256>>>(bias, out);
}